// round 9
// baseline (speedup 1.0000x reference)
#include <cuda_runtime.h>
#include <math.h>

#define SAC_WARMUP 365
#define PF 4

// ---- two-lane scalar pair: two basins' chains interleave in the issue slots ----
struct f2 { float a, b; };
__device__ __forceinline__ f2 F2(float v) { f2 r; r.a = v; r.b = v; return r; }
__device__ __forceinline__ f2 F2(float x, float y) { f2 r; r.a = x; r.b = y; return r; }
__device__ __forceinline__ f2 operator+(f2 u, f2 v) { return F2(u.a + v.a, u.b + v.b); }
__device__ __forceinline__ f2 operator-(f2 u, f2 v) { return F2(u.a - v.a, u.b - v.b); }
__device__ __forceinline__ f2 operator*(f2 u, f2 v) { return F2(u.a * v.a, u.b * v.b); }
__device__ __forceinline__ f2 min2(f2 u, f2 v) { return F2(fminf(u.a, v.a), fminf(u.b, v.b)); }
__device__ __forceinline__ f2 max2(f2 u, f2 v) { return F2(fmaxf(u.a, v.a), fmaxf(u.b, v.b)); }
__device__ __forceinline__ f2 relu2(f2 u) { return F2(fmaxf(u.a, 0.f), fmaxf(u.b, 0.f)); }
// defr^rexp via MUFU lg2/ex2 per lane; lg2(0)=-inf -> ex2(-inf)=0 (matches 0^r, r>=1)
__device__ __forceinline__ f2 powr2(f2 x, f2 r) {
    float la, lb, ea, eb;
    asm("lg2.approx.f32 %0, %1;" : "=f"(la) : "f"(x.a));
    asm("lg2.approx.f32 %0, %1;" : "=f"(lb) : "f"(x.b));
    la *= r.a; lb *= r.b;
    asm("ex2.approx.f32 %0, %1;" : "=f"(ea) : "f"(la));
    asm("ex2.approx.f32 %0, %1;" : "=f"(eb) : "f"(lb));
    return F2(ea, eb);
}
// rcp.approx + 1 Newton step per lane; off the carry-critical path
__device__ __forceinline__ f2 rcp2(f2 x) {
    float ra, rb;
    asm("rcp.approx.f32 %0, %1;" : "=f"(ra) : "f"(x.a));
    asm("rcp.approx.f32 %0, %1;" : "=f"(rb) : "f"(x.b));
    ra = ra * (2.0f - x.a * ra);
    rb = rb * (2.0f - x.b * rb);
    return F2(ra, rb);
}

// BC > 0: compile-time B2 (pair count) for strength-reduced addressing.
template <int B2C>
__global__ __launch_bounds__(128, 1)
void sac4dpl_kernel(const float* __restrict__ p_and_e,   // [T, B, 2]
                    const float* __restrict__ params,    // [B, 21]
                    float* __restrict__ out,             // [2, T-WARMUP, B]
                    int T, int B2rt)
{
    const int B2 = (B2C > 0) ? B2C : B2rt;      // basin pairs
    int tb = blockIdx.x * 128 + threadIdx.x;
    if (tb >= B2) return;

    // ---- load + scale parameters for both lanes ----
    const float lo[21] = {0.1f, 0.0f, 0.0f, 10.0f, 10.0f, 50.0f, 10.0f, 50.0f,
                          0.0f, 0.0f, 0.0f, 5.0f, 1.0f, 0.1f, 0.01f, 0.001f,
                          0.5f, 0.95f, 0.98f, 0.0f, 0.0f};
    const float hi[21] = {1.2f, 0.1f, 0.3f, 100.0f, 100.0f, 400.0f, 100.0f, 1000.0f,
                          0.3f, 0.5f, 0.1f, 350.0f, 4.0f, 0.5f, 0.35f, 0.05f,
                          0.9f, 0.998f, 0.998f, 1.0f, 0.5f};
    f2 pr[21];
#pragma unroll
    for (int i = 0; i < 21; i++) {
        pr[i].a = lo[i] + params[(size_t)(tb * 2)     * 21 + i] * (hi[i] - lo[i]);
        pr[i].b = lo[i] + params[(size_t)(tb * 2 + 1) * 21 + i] * (hi[i] - lo[i]);
    }

    const f2 kc    = pr[0],  pctim = pr[1],  adimp = pr[2];
    const f2 uztwm = pr[3],  uzfwm = pr[4],  lztwm = pr[5];
    const f2 lzfsm = pr[6],  lzfpm = pr[7];
    const f2 pfree = pr[9],  riva  = pr[10];
    const f2 zperc = pr[11], rexp  = pr[12], uzk = pr[13];
    const f2 lzsk  = pr[14], lzpk  = pr[15];
    const f2 ci    = pr[16], cgs   = pr[17], cgp = pr[18];
    const f2 ke    = pr[19], xe    = pr[20];

    const f2 one = F2(1.0f);
    const f2 r_uztwm = rcp2(uztwm);
    const f2 r_lztwm = rcp2(lztwm);
    const f2 r_ulz   = rcp2(uztwm + lztwm);
    const f2 r_lzfsm = rcp2(lzfsm);
    const f2 r_lzfpm = rcp2(lzfpm);
    const f2 sfm     = lzfsm + lzfpm;
    const f2 lzsum   = sfm + lztwm;
    const f2 r_lzsum = rcp2(lzsum);
    const f2 uzsum   = uztwm + uzfwm;
    const f2 pbase   = lzfsm * lzsk + lzfpm * lzpk;
    const f2 parea   = one - pctim - adimp;
    const f2 fp2     = F2(2.0f) * (lzfpm * rcp2(sfm));
    const f2 pbu     = pbase * rcp2(uzfwm);
    const f2 pbuz    = pbu * zperc;
    const f2 ci1     = (one - ci)  * parea;
    const f2 cgs1    = (one - cgs) * parea;
    const f2 cgp1    = (one - cgp) * parea;
    const f2 dt      = F2(0.5f);
    const f2 rmden   = rcp2(ke * (one - xe) + dt);
    const f2 c1      = (ke * xe + dt) * rmden;
    const f2 c2      = (dt - ke * xe) * rmden;
    const f2 c3      = (ke * (one - xe) - dt) * rmden;

    // ---- initial carry ----
    f2 auztw = F2(0.01f);
    f2 alztw = auztw, uztw = auztw, uzfw = auztw, lztw = auztw;
    f2 lzfs = auztw, lzfp = auztw;
    f2 qs = auztw, qi = auztw, qgs = auztw, qgp = auztw, o1 = auztw;
    f2 o2 = auztw, et = auztw;

    const float4* __restrict__ pe4 = (const float4*)p_and_e + tb;   // (p0,e0,p1,e1); stride B2
    const int nout = T - SAC_WARMUP;
    float2* __restrict__ qout = (float2*)out + tb;                   // stride B2
    float2* __restrict__ eout = (float2*)(out + (size_t)nout * (2 * B2)) + tb;

    float4 buf[PF];
#pragma unroll
    for (int i = 0; i < PF; i++)
        buf[i] = pe4[(size_t)i * B2];
    const float4* __restrict__ pe_pf = pe4 + (size_t)PF * B2;

    // Lean step (redundant clamps removed per R8 invariants); inputs are >=0
    // by construction so p/e need no clamp.
#define SAC_BODY(cur)                                                          \
    do {                                                                       \
        f2 p = F2((cur).x, (cur).z);                                           \
        f2 e = F2((cur).y, (cur).w);                                           \
        f2 ep    = kc * e;                                                     \
        f2 roimp = pctim * p;                                                  \
        f2 ae2   = pctim * ep;                                                 \
        f2 ae1    = min2(auztw, ep * (auztw * r_uztwm));                       \
        f2 ae3    = (ep - ae1) * (alztw * r_ulz);                              \
        f2 pav    = relu2(p - (uztwm - (auztw - ae1)));                        \
        f2 almae3 = alztw - ae3;                                               \
        f2 adsur  = pav * (almae3 * r_lztwm);                                  \
        f2 pam    = pav - adsur + almae3;                                      \
        f2 ars    = relu2(pam - lztwm);                                        \
        f2 auztw_n = min2(uztwm, auztw - ae1 + p);                             \
        f2 alztw_n = min2(lztwm, pam);                                         \
        f2 e1  = min2(uztw, ep * (uztw * r_uztwm));                            \
        f2 e2  = min2(uzfw, ep - e1);                                          \
        f2 e3  = (ep - e1 - e2) * (lztw * r_ulz);                              \
        f2 lt1 = lztw - e3;                                                    \
        f2 e4  = riva * ep;                                                    \
        et = ae2 + ae1 + ae3 + e1 + e2 + e3 + e4;                              \
        f2 uzres = p + (uztw + uzfw - e1 - e2);                                \
        f2 rs = relu2(uzres - uzsum) * parea;                                  \
        f2 ut = min2(uztwm, uztw - e1 + p);                                    \
        f2 uf = min2(uzfwm, uzres - ut);                                       \
        f2 ri = uf * uzk;                                                      \
        uf = uf - ri;                                                          \
        f2 gp = one - lzfp * r_lzfpm;                                          \
        f2 gs = one - lzfs * r_lzfsm;                                          \
        f2 coef = min2(fp2 * gp * rcp2(gp + gs), one);                         \
        f2 lzdef = lzfs + lzfp + lt1;                                          \
        f2 defr  = relu2(one - lzdef * r_lzsum);                               \
        f2 pw    = powr2(defr, rexp);                                          \
        f2 perc  = (pbu + pbuz * pw) * uf;                                     \
        f2 rate  = min2(perc, lzsum - lzdef);                                  \
        uf = relu2(uf - rate);                                                 \
        f2 fx    = min2(sfm - (lzfs + lzfp),                                   \
                        max2(rate - (lztwm - lt1), rate * pfree));             \
        f2 perct = rate - fx;                                                  \
        f2 percp = min2(lzfpm - lzfp,                                          \
                        max2(fx - (lzfsm - lzfs), coef * fx));                 \
        f2 percs = fx - percp;                                                 \
        f2 lt = min2(lt1 + perct, lztwm);                                      \
        f2 ls = lzfs + percs;                                                  \
        f2 lp = lzfp + percp;                                                  \
        f2 rgs = ls * lzsk;  ls = ls - rgs;                                    \
        f2 rgp = lp * lzpk;  lp = lp - rgp;                                    \
        f2 i1   = qs + qi + qgs + qgp;                                         \
        f2 qs_n = roimp + (adsur + ars) * adimp + rs;                          \
        f2 qi_n = ci  * qi  + ci1  * ri;                                       \
        f2 qgs_n = cgs * qgs + cgs1 * rgs;                                     \
        f2 qgp_n = cgp * qgp + cgp1 * rgp;                                     \
        f2 i2   = qs_n + qi_n + qgs_n + qgp_n;                                 \
        o2 = c1 * i1 + c2 * i2 + c3 * o1;                                      \
        auztw = auztw_n; alztw = alztw_n;                                      \
        uztw = ut; uzfw = uf; lztw = lt; lzfs = ls; lzfp = lp;                 \
        qs = qs_n; qi = qi_n; qgs = qgs_n; qgp = qgp_n;                        \
        o1 = o2;                                                               \
    } while (0)

    // ---- phase 1: warmup — no stores, unconditional prefetch ----
#pragma unroll 4
    for (int t = 0; t < SAC_WARMUP; ++t) {
        float4 cur = buf[t & (PF - 1)];
        buf[t & (PF - 1)] = *pe_pf;  pe_pf += B2;
        SAC_BODY(cur);
    }

    // ---- phase 2: main — unconditional stores AND prefetch ----
#pragma unroll 4
    for (int t = SAC_WARMUP; t < T - PF; ++t) {
        float4 cur = buf[t & (PF - 1)];
        buf[t & (PF - 1)] = *pe_pf;  pe_pf += B2;
        SAC_BODY(cur);
        *qout = make_float2(o2.a, o2.b);  qout += B2;
        *eout = make_float2(et.a, et.b);  eout += B2;
    }

    // ---- phase 3: tail — last PF steps, no prefetch ----
#pragma unroll
    for (int t = T - PF; t < T; ++t) {
        float4 cur = buf[t & (PF - 1)];
        SAC_BODY(cur);
        *qout = make_float2(o2.a, o2.b);  qout += B2;
        *eout = make_float2(et.a, et.b);  eout += B2;
    }
#undef SAC_BODY
}

extern "C" void kernel_launch(void* const* d_in, const int* in_sizes, int n_in,
                              void* d_out, int out_size)
{
    const float* p_and_e = (const float*)d_in[0];   // [T, B, 2]
    const float* params  = (const float*)d_in[1];   // [B, 21]
    float* out = (float*)d_out;

    int B = in_sizes[1] / 21;
    int T = in_sizes[0] / (2 * B);

    int B2 = B / 2;
    int grid = (B2 + 127) / 128;   // 40 blocks for B=10000 -> 1 warp/SMSP
    if (B2 == 5000)
        sac4dpl_kernel<5000><<<grid, 128>>>(p_and_e, params, out, T, B2);
    else
        sac4dpl_kernel<0><<<grid, 128>>>(p_and_e, params, out, T, B2);
}

// round 10
// speedup vs baseline: 1.2547x; 1.2547x over previous
#include <cuda_runtime.h>
#include <math.h>

#define SAC_WARMUP 365
#define PF 4

__device__ __forceinline__ float fast_lg2(float x) {
    float r; asm("lg2.approx.f32 %0, %1;" : "=f"(r) : "f"(x)); return r;
}
__device__ __forceinline__ float fast_ex2(float x) {
    float r; asm("ex2.approx.f32 %0, %1;" : "=f"(r) : "f"(x)); return r;
}
// rcp.approx + 1 Newton step; entirely inside the carry-only preamble
__device__ __forceinline__ float fast_rcp(float d) {
    float r; asm("rcp.approx.f32 %0, %1;" : "=f"(r) : "f"(d));
    r = r * (2.0f - d * r);
    return r;
}

template <int BC>
__global__ __launch_bounds__(128, 1)
void sac4dpl_kernel(const float* __restrict__ p_and_e,   // [T, B, 2]
                    const float* __restrict__ params,    // [B, 21]
                    float* __restrict__ out,             // [2, T-WARMUP, B]
                    int T, int Brt)
{
    const int B = (BC > 0) ? BC : Brt;
    int b = blockIdx.x * 128 + threadIdx.x;
    if (b >= B) return;

    // ---- load + scale parameters (one-time) ----
    const float lo[21] = {0.1f, 0.0f, 0.0f, 10.0f, 10.0f, 50.0f, 10.0f, 50.0f,
                          0.0f, 0.0f, 0.0f, 5.0f, 1.0f, 0.1f, 0.01f, 0.001f,
                          0.5f, 0.95f, 0.98f, 0.0f, 0.0f};
    const float hi[21] = {1.2f, 0.1f, 0.3f, 100.0f, 100.0f, 400.0f, 100.0f, 1000.0f,
                          0.3f, 0.5f, 0.1f, 350.0f, 4.0f, 0.5f, 0.35f, 0.05f,
                          0.9f, 0.998f, 0.998f, 1.0f, 0.5f};
    float pr[21];
#pragma unroll
    for (int i = 0; i < 21; i++)
        pr[i] = lo[i] + params[(size_t)b * 21 + i] * (hi[i] - lo[i]);

    const float kc    = pr[0],  pctim = pr[1],  adimp = pr[2];
    const float uztwm = pr[3],  uzfwm = pr[4],  lztwm = pr[5];
    const float lzfsm = pr[6],  lzfpm = pr[7];
    const float pfree = pr[9],  riva  = pr[10];
    const float zperc = pr[11], rexp  = pr[12], uzk = pr[13];
    const float lzsk  = pr[14], lzpk  = pr[15];
    const float ci    = pr[16], cgs   = pr[17], cgp = pr[18];
    const float ke    = pr[19], xe    = pr[20];

    const float r_uztwm = 1.0f / uztwm;
    const float r_lztwm = 1.0f / lztwm;
    const float r_ulz   = 1.0f / (uztwm + lztwm);
    const float r_lzfsm = 1.0f / lzfsm;
    const float r_lzfpm = 1.0f / lzfpm;
    const float sfm     = lzfsm + lzfpm;
    const float lzsum   = sfm + lztwm;
    const float r_lzsum = 1.0f / lzsum;
    const float uzsum   = uztwm + uzfwm;
    const float pbase   = lzfsm * lzsk + lzfpm * lzpk;
    const float parea   = 1.0f - pctim - adimp;
    const float fp2     = 2.0f * (lzfpm / sfm);
    const float pbu     = pbase / uzfwm;
    const float pbuz    = pbu * zperc;
    const float ci1     = (1.0f - ci)  * parea;
    const float cgs1    = (1.0f - cgs) * parea;
    const float cgp1    = (1.0f - cgp) * parea;
    const float dt      = 0.5f;
    const float mden    = ke * (1.0f - xe) + dt;
    const float c1      = (ke * xe + dt) / mden;
    const float c2      = (dt - ke * xe) / mden;
    const float c3      = (ke * (1.0f - xe) - dt) / mden;

    // ---- initial carry ----
    float auztw = 0.01f, alztw = 0.01f;
    float uztw  = 0.01f, uzfw  = 0.01f;
    float lztw  = 0.01f, lzfs  = 0.01f, lzfp = 0.01f;
    float qs = 0.01f, qi = 0.01f, qgs = 0.01f, qgp = 0.01f;
    float o1 = 0.01f;
    float o2 = 0.01f, et = 0.01f;

    const float2* __restrict__ pe  = (const float2*)p_and_e + b;
    const int nout = T - SAC_WARMUP;
    float* __restrict__ qout = out + b;
    float* __restrict__ eout = out + (size_t)nout * B + b;

    float2 buf[PF];
#pragma unroll
    for (int i = 0; i < PF; i++)
        buf[i] = pe[(size_t)i * B];
    const float2* __restrict__ pe_pf = pe + (size_t)PF * B;

    // DAG-widened step: carry-only preamble first (schedulable against the
    // input-dependent chain), tree-reassociated folds, shared ep*r_uztwm.
    // Clamp eliminations per R8 invariants; lg2 domain guard on defr kept.
#define SAC_BODY(cur)                                                          \
    do {                                                                       \
        /* ---- carry-only preamble: independent work for the scheduler ---- */\
        float uzw_sum = uztw + uzfw;                                           \
        float lzfsp   = lzfs + lzfp;                                           \
        float uma     = auztw - uztwm;                                         \
        float aru     = alztw * r_ulz;                                         \
        float lru     = lztw  * r_ulz;                                         \
        float sfm_l   = sfm   - lzfsp;                                         \
        float lzfpm_l = lzfpm - lzfp;                                          \
        float lzfsm_l = lzfsm - lzfs;                                          \
        float gp = 1.0f - lzfp * r_lzfpm;                                      \
        float gs = 1.0f - lzfs * r_lzfsm;                                      \
        float coef = fminf(fp2 * gp * fast_rcp(gp + gs), 1.0f);                \
        float i1   = (qs + qi) + (qgs + qgp);                                  \
        float mpre = c1 * i1 + c3 * o1;      /* o2 = c2*i2 + mpre */           \
        /* ---- input-dependent chain ---- */                                  \
        float p = fmaxf((cur).x, 0.0f);                                        \
        float e = fmaxf((cur).y, 0.0f);                                        \
        float ep    = kc * e;                                                  \
        float epru  = ep * r_uztwm;                                            \
        float roimp = pctim * p;                                               \
        float ae2   = pctim * ep;                                              \
        float ae1   = fminf(auztw, epru * auztw);                              \
        float e1    = fminf(uztw,  epru * uztw);                               \
        float ae3   = (ep - ae1) * aru;                                        \
        float pav   = fmaxf((p + uma) - ae1, 0.0f);                            \
        float almae3 = alztw - ae3;                                            \
        float adsur = pav * (almae3 * r_lztwm);                                \
        float pam   = (pav - adsur) + almae3;                                  \
        float ars   = fmaxf(pam - lztwm, 0.0f);                                \
        float auztw_n = fminf(uztwm, (auztw - ae1) + p);                       \
        float alztw_n = fminf(lztwm, pam);                                     \
        float e2  = fminf(uzfw, ep - e1);                                      \
        float e12 = e1 + e2;                                                   \
        float e3  = (ep - e12) * lru;                                          \
        float lt1 = lztw - e3;                                                 \
        float e4  = riva * ep;                                                 \
        et = ((ae2 + ae1) + (ae3 + e1)) + ((e2 + e3) + e4);                    \
        float uzres = p + (uzw_sum - e12);                                     \
        float rs = fmaxf(uzres - uzsum, 0.0f) * parea;                         \
        float ut = fminf(uztwm, (uztw + p) - e1);                              \
        float uf = fminf(uzfwm, uzres - ut);                                   \
        float ri = uf * uzk;                                                   \
        uf = uf - ri;                                                          \
        float lzdef = lzfsp + lt1;                                             \
        float defr  = fmaxf(1.0f - lzdef * r_lzsum, 0.0f);                     \
        float pw    = fast_ex2(rexp * fast_lg2(defr));                         \
        float perc  = (pbu + pbuz * pw) * uf;                                  \
        float rate  = fminf(perc, lzsum - lzdef);                              \
        uf = fmaxf(uf - rate, 0.0f);                                           \
        float fx    = fminf(sfm_l,                                             \
                            fmaxf(rate - (lztwm - lt1), rate * pfree));        \
        float perct = rate - fx;                                               \
        float percp = fminf(lzfpm_l, fmaxf(fx - lzfsm_l, coef * fx));          \
        float percs = fx - percp;                                              \
        float lt = fminf(lt1 + perct, lztwm);                                  \
        float ls = lzfs + percs;                                               \
        float lp = lzfp + percp;                                               \
        float rgs = ls * lzsk;  ls = ls - rgs;                                 \
        float rgp = lp * lzpk;  lp = lp - rgp;                                 \
        float qs_n = (roimp + rs) + (adsur + ars) * adimp;                     \
        float qi_n = ci  * qi  + ci1  * ri;                                    \
        float qgs_n = cgs * qgs + cgs1 * rgs;                                  \
        float qgp_n = cgp * qgp + cgp1 * rgp;                                  \
        float i2   = (qs_n + qi_n) + (qgs_n + qgp_n);                          \
        o2 = c2 * i2 + mpre;                                                   \
        auztw = auztw_n; alztw = alztw_n;                                      \
        uztw = ut; uzfw = uf; lztw = lt; lzfs = ls; lzfp = lp;                 \
        qs = qs_n; qi = qi_n; qgs = qgs_n; qgp = qgp_n;                        \
        o1 = o2;                                                               \
    } while (0)

    // ---- phase 1: warmup — no stores, unconditional prefetch ----
#pragma unroll 4
    for (int t = 0; t < SAC_WARMUP; ++t) {
        float2 cur = buf[t & (PF - 1)];
        buf[t & (PF - 1)] = *pe_pf;  pe_pf += B;
        SAC_BODY(cur);
    }

    // ---- phase 2: main — unconditional stores AND prefetch ----
#pragma unroll 4
    for (int t = SAC_WARMUP; t < T - PF; ++t) {
        float2 cur = buf[t & (PF - 1)];
        buf[t & (PF - 1)] = *pe_pf;  pe_pf += B;
        SAC_BODY(cur);
        *qout = o2;  qout += B;
        *eout = et;  eout += B;
    }

    // ---- phase 3: tail — last PF steps, no prefetch ----
#pragma unroll
    for (int t = T - PF; t < T; ++t) {
        float2 cur = buf[t & (PF - 1)];
        SAC_BODY(cur);
        *qout = o2;  qout += B;
        *eout = et;  eout += B;
    }
#undef SAC_BODY
}

extern "C" void kernel_launch(void* const* d_in, const int* in_sizes, int n_in,
                              void* d_out, int out_size)
{
    const float* p_and_e = (const float*)d_in[0];   // [T, B, 2]
    const float* params  = (const float*)d_in[1];   // [B, 21]
    float* out = (float*)d_out;

    int B = in_sizes[1] / 21;
    int T = in_sizes[0] / (2 * B);

    int grid = (B + 127) / 128;
    if (B == 10000)
        sac4dpl_kernel<10000><<<grid, 128>>>(p_and_e, params, out, T, B);
    else
        sac4dpl_kernel<0><<<grid, 128>>>(p_and_e, params, out, T, B);
}